// round 13
// baseline (speedup 1.0000x reference)
#include <cuda_runtime.h>
#include <cstdint>
#include <cstddef>

// Problem dims
#define BB    64
#define TT    512
#define IDIM  512
#define HH    512
#define RING  8

// Tiling
#define TM    16
#define TN    32
#define NBAND (BB/TM)       // 4
#define NQ    (HH/TN)       // 16 (CTA-level releases)
#define NCTA  128
#define NTHR  256

#define AS_STRIDE 1028
#define RMS 34              // Red m-stride
#define RWS (16*RMS)        // 544 floats per warp slice

// SMEM layout (floats): As | Ws | Red[2]
#define AS_OFF  0
#define WS_OFF  (TM*AS_STRIDE)              // 16448
#define RED_OFF (WS_OFF + 512*64)           // + 32768
#define SMEM_FLOATS (RED_OFF + 2*8*RWS)     // + 8704 = 57920 floats (~231.7 KB)

// Named barriers
#define BAR_RDY0  1
#define BAR_RDY1  2
#define BAR_FREE0 3
#define BAR_FREE1 4
#define BAR_ONJ   5

__device__ float g_h1[RING][BB][HH];
__device__ int   g_done1[TT*NBAND];
__device__ int   g_done2[TT*NBAND];

__global__ void rnn_init_counters() {
    int i = blockIdx.x * blockDim.x + threadIdx.x;
    if (i < TT*NBAND) { g_done1[i] = 0; g_done2[i] = 0; }
}

__device__ __forceinline__ int ld_acq(const int* p) {
    int v;
    asm volatile("ld.acquire.gpu.global.u32 %0, [%1];" : "=r"(v) : "l"(p));
    return v;
}
__device__ __forceinline__ void red_release(int* p) {
    asm volatile("red.release.gpu.global.add.u32 [%0], %1;" :: "l"(p), "r"(1) : "memory");
}
__device__ __forceinline__ void spin_ge(const int* p, int target) {
    while (ld_acq(p) < target) { }
}
__device__ __forceinline__ void bar_sync(int id, int cnt) {
    asm volatile("bar.sync %0, %1;" :: "r"(id), "r"(cnt) : "memory");
}
__device__ __forceinline__ void bar_arrive(int id, int cnt) {
    asm volatile("bar.arrive %0, %1;" :: "r"(id), "r"(cnt) : "memory");
}
__device__ __forceinline__ void fma2(unsigned long long& acc,
                                     unsigned long long a, unsigned long long b) {
    asm("fma.rn.f32x2 %0, %1, %2, %0;" : "+l"(acc) : "l"(a), "l"(b));
}
__device__ __forceinline__ float4 ldcg4(const float* p) {
    return __ldcg((const float4*)p);
}

// tanh(x) = 1 - 2/(exp(2x)+1); ex2.approx + rcp.approx + 1 Newton (abs err ~1e-7)
__device__ __forceinline__ float fast_tanh(float v) {
    float e;
    asm("ex2.approx.f32 %0, %1;" : "=f"(e) : "f"(v * 2.8853900817779268f));
    float d = e + 1.0f;
    float r;
    asm("rcp.approx.f32 %0, %1;" : "=f"(r) : "f"(d));
    r = r * (2.0f - d * r);
    return 1.0f - 2.0f * r;
}

// Store one float4 (k = 4*kk..4*kk+3 of row mm) into swizzled row-major As.
__device__ __forceinline__ void stage_f4(float* As, int mm, int kk, float4 v) {
    int idx = (kk*4) ^ ((mm >> 2) * 8);
    *(float4*)&As[mm*AS_STRIDE + idx] = v;
}

// R11 GEMM micro-kernel: warp kp-slice [64w,64w+64), thread 4x4, partials to RedP.
__device__ __forceinline__ void gemm_and_partials(
    const float* __restrict__ Ab, const float* __restrict__ Ws,
    float* __restrict__ RedP, int w, int rg, int cg, int xr)
{
    unsigned long long acc[16];
    #pragma unroll
    for (int i = 0; i < 16; ++i) acc[i] = 0ull;

    const float* Wp = Ws + (size_t)(64*w)*64 + cg*4;
    #pragma unroll 4
    for (int kpl = 0; kpl < 64; ++kpl) {
        int ks = (2*(64*w + kpl)) ^ xr;
        unsigned long long a0 = *(const unsigned long long*)(Ab + ks);
        unsigned long long a1 = *(const unsigned long long*)(Ab + AS_STRIDE   + ks);
        unsigned long long a2 = *(const unsigned long long*)(Ab + 2*AS_STRIDE + ks);
        unsigned long long a3 = *(const unsigned long long*)(Ab + 3*AS_STRIDE + ks);
        ulonglong2 W0 = *(const ulonglong2*)(Wp);        // cols 2cg, 2cg+1
        ulonglong2 W1 = *(const ulonglong2*)(Wp + 32);   // cols 16+2cg, 17+2cg
        fma2(acc[ 0], a0, W0.x); fma2(acc[ 1], a0, W0.y);
        fma2(acc[ 2], a0, W1.x); fma2(acc[ 3], a0, W1.y);
        fma2(acc[ 4], a1, W0.x); fma2(acc[ 5], a1, W0.y);
        fma2(acc[ 6], a1, W1.x); fma2(acc[ 7], a1, W1.y);
        fma2(acc[ 8], a2, W0.x); fma2(acc[ 9], a2, W0.y);
        fma2(acc[10], a2, W1.x); fma2(acc[11], a2, W1.y);
        fma2(acc[12], a3, W0.x); fma2(acc[13], a3, W0.y);
        fma2(acc[14], a3, W1.x); fma2(acc[15], a3, W1.y);
        Wp += 64;
    }

    float s[16];
    #pragma unroll
    for (int i = 0; i < 16; ++i) {
        float lo, hi;
        asm("mov.b64 {%0, %1}, %2;" : "=f"(lo), "=f"(hi) : "l"(acc[i]));
        s[i] = lo + hi;
    }
    float* Rw = RedP + w*RWS + (4*rg)*RMS + cg*2;
    #pragma unroll
    for (int i = 0; i < 4; ++i) {
        *(float2*)(Rw + i*RMS)      = make_float2(s[i*4+0], s[i*4+1]);
        *(float2*)(Rw + i*RMS + 16) = make_float2(s[i*4+2], s[i*4+3]);
    }
}

__global__ void __launch_bounds__(NTHR, 1) rnn_persistent(
    const float* __restrict__ x,    // [B,T,I]
    const float* __restrict__ h0,   // [L,B,H]
    const float* __restrict__ Wih,  // [L,H,I]
    const float* __restrict__ bih,  // [L,H]
    const float* __restrict__ Whh,  // [L,H,H]
    const float* __restrict__ bhh,  // [L,H]
    float* __restrict__ out)        // [B,T,H] then [L,B,H]
{
    extern __shared__ float smem[];
    float* As   = smem + AS_OFF;   // [16][1028] row-major, k-index XOR-swizzled
    float* Ws   = smem + WS_OFF;   // [512 kp][64]
    float* Red0 = smem + RED_OFF;  // 2 x [8 w][16 m x RMS], parity buffers

    const int bx    = blockIdx.x;
    const int layer = bx >> 6;
    const int j     = bx & 63;
    const int r     = j >> 4;
    const int q     = j & 15;
    const int tid   = threadIdx.x;
    const int w     = tid >> 5;          // warp id; GEMM kp slice [64w, 64w+64)
    const int lane  = tid & 31;
    const int rg    = lane & 3;
    const int cg    = lane >> 2;
    const bool off_g = (w < 4);          // warps 0-3: off-path producers

    const float* Wi = Wih + (size_t)layer * HH * IDIM;
    const float* Wh = Whh + (size_t)layer * HH * HH;

    // one-time weight load: k-paired transposed; kp 0..255 = Wih, 256..511 = Whh
    for (int idx = tid; idx < TN*256; idx += NTHR) {
        int c   = idx >> 8;
        int kpl = idx & 255;
        float2 vi = __ldg((const float2*)(Wi + (size_t)(q*TN + c)*IDIM) + kpl);
        float2 vh = __ldg((const float2*)(Wh + (size_t)(q*TN + c)*HH)   + kpl);
        *(float2*)&Ws[(size_t)kpl*64 + c*2]       = vi;
        *(float2*)&Ws[(size_t)(256+kpl)*64 + c*2] = vh;
    }

    // per-warp staging constants: warp w owns As f4-columns [32w, 32w+32)
    const int c_st  = lane & 15;
    const int mr_st = lane >> 4;
    const int kk0   = 32*w + c_st;
    const int kk1   = kk0 + 16;
    const int s0    = off_g ? kk0 : (kk0 - 128);
    const int s1    = off_g ? kk1 : (kk1 - 128);

    // ON-group output mapping: 4 outputs per ON thread
    const int ln    = tid & 127;
    const int m_on  = ln >> 3;
    const int c_on  = 4*(ln & 7);
    const int brow_on = r*TM + m_on;
    const int hcol_on = q*TN + c_on;
    float4 bias4;
    bias4.x = bih[layer*HH + hcol_on+0] + bhh[layer*HH + hcol_on+0];
    bias4.y = bih[layer*HH + hcol_on+1] + bhh[layer*HH + hcol_on+1];
    bias4.z = bih[layer*HH + hcol_on+2] + bhh[layer*HH + hcol_on+2];
    bias4.w = bih[layer*HH + hcol_on+3] + bhh[layer*HH + hcol_on+3];

    __syncthreads();

    const float* Ab = As + (4*rg)*AS_STRIDE;
    const int    xr = 8*rg;

    if (off_g) {
        // ================= OFF group: warps 0-3 (kp 0..255) =================
        for (int t = 0; t < TT; ++t) {
            const int p = t & 1;
            if (t >= 2) bar_sync(BAR_FREE0 + p, 256);   // Red[p] consumed (t-2)

            if (layer == 0) {
                #pragma unroll
                for (int i = 0; i < 8; ++i) {
                    int mm = mr_st + 2*i;
                    const float4* xp = (const float4*)(x + ((size_t)(r*TM+mm)*TT + t)*IDIM);
                    stage_f4(As, mm, kk0, __ldg(xp + s0));
                    stage_f4(As, mm, kk1, __ldg(xp + s1));
                }
            } else {
                if (lane == 0) spin_ge(&g_done1[t*NBAND + r], NQ);
                __syncwarp();
                const float* hb = &g_h1[t&(RING-1)][r*TM][0];
                #pragma unroll
                for (int i = 0; i < 8; ++i) {
                    int mm = mr_st + 2*i;
                    const float* hp = hb + (size_t)mm*HH;
                    stage_f4(As, mm, kk0, ldcg4(hp + s0*4));
                    stage_f4(As, mm, kk1, ldcg4(hp + s1*4));
                }
            }
            __syncwarp();
            gemm_and_partials(Ab, Ws, Red0 + p*(8*RWS), w, rg, cg, xr);
            bar_arrive(BAR_RDY0 + p, 256);              // partials for t published
        }
    } else {
        // ================= ON group: warps 4-7 (kp 256..511, recurrent) =================
        for (int t = 0; t < TT; ++t) {
            const int p = t & 1;

            if (layer == 0) {
                if (lane == 0) {
                    if (t > 0)     spin_ge(&g_done1[(t-1)*NBAND + r], NQ);
                    if (t >= RING) spin_ge(&g_done2[(t-RING)*NBAND + r], NQ);
                }
                __syncwarp();
                #pragma unroll
                for (int i = 0; i < 8; ++i) {
                    int mm = mr_st + 2*i;
                    int b  = r*TM + mm;
                    const float* hp = (t == 0) ? (h0 + (size_t)b*HH)
                                               : &g_h1[(t-1)&(RING-1)][b][0];
                    stage_f4(As, mm, kk0, ldcg4(hp + s0*4));
                    stage_f4(As, mm, kk1, ldcg4(hp + s1*4));
                }
            } else {
                if (lane == 0 && t > 0) spin_ge(&g_done2[(t-1)*NBAND + r], NQ);
                __syncwarp();
                #pragma unroll
                for (int i = 0; i < 8; ++i) {
                    int mm = mr_st + 2*i;
                    int b  = r*TM + mm;
                    const float* hp = (t == 0) ? (h0 + (size_t)BB*HH + (size_t)b*HH)
                                               : (out + ((size_t)b*TT + (t-1))*HH);
                    stage_f4(As, mm, kk0, ldcg4(hp + s0*4));
                    stage_f4(As, mm, kk1, ldcg4(hp + s1*4));
                }
            }
            __syncwarp();
            float* RedP = Red0 + p*(8*RWS);
            gemm_and_partials(Ab, Ws, RedP, w, rg, cg, xr);

            bar_sync(BAR_RDY0 + p, 256);                // join with OFF partials for t

            // ---- reduce 8 slices (4 outputs), bias, tanh, store ----
            float2 aA = make_float2(0.f, 0.f), aB = make_float2(0.f, 0.f);
            const float* Rb = RedP + m_on*RMS + c_on;
            #pragma unroll
            for (int ww = 0; ww < 8; ++ww) {
                float2 v0 = *(const float2*)(Rb + ww*RWS);
                float2 v1 = *(const float2*)(Rb + ww*RWS + 2);
                aA.x += v0.x; aA.y += v0.y; aB.x += v1.x; aB.y += v1.y;
            }
            float4 res;
            res.x = fast_tanh(aA.x + bias4.x);
            res.y = fast_tanh(aA.y + bias4.y);
            res.z = fast_tanh(aB.x + bias4.z);
            res.w = fast_tanh(aB.y + bias4.w);

            if (layer == 0) {
                *(float4*)&g_h1[t&(RING-1)][brow_on][hcol_on] = res;
                if (t == TT-1)
                    *(float4*)(out + (size_t)BB*TT*HH + (size_t)brow_on*HH + hcol_on) = res;
            } else {
                *(float4*)(out + ((size_t)brow_on*TT + t)*HH + hcol_on) = res;
                if (t == TT-1)
                    *(float4*)(out + (size_t)BB*TT*HH + (size_t)BB*HH
                                   + (size_t)brow_on*HH + hcol_on) = res;
            }

            bar_sync(BAR_ONJ, 128);                     // ON stores done
            if (ln == 0) {
                int* ctr = (layer == 0) ? &g_done1[t*NBAND + r] : &g_done2[t*NBAND + r];
                red_release(ctr);
            }
            bar_arrive(BAR_FREE0 + p, 256);             // Red[p] free for t+2
        }
    }
}

extern "C" void kernel_launch(void* const* d_in, const int* in_sizes, int n_in,
                              void* d_out, int out_size)
{
    const float* x   = (const float*)d_in[0];
    const float* h0  = (const float*)d_in[1];
    const float* Wih = (const float*)d_in[2];
    const float* bih = (const float*)d_in[3];
    const float* Whh = (const float*)d_in[4];
    const float* bhh = (const float*)d_in[5];
    float* out = (float*)d_out;

    const size_t smem_bytes = (size_t)SMEM_FLOATS * sizeof(float); // ~231.7 KB
    cudaFuncSetAttribute(rnn_persistent,
                         cudaFuncAttributeMaxDynamicSharedMemorySize,
                         (int)smem_bytes);

    rnn_init_counters<<<(TT*NBAND + 255)/256, 256>>>();
    rnn_persistent<<<NCTA, NTHR, smem_bytes>>>(x, h0, Wih, bih, Whh, bhh, out);
}

// round 14
// speedup vs baseline: 1.4638x; 1.4638x over previous
#include <cuda_runtime.h>
#include <cstdint>
#include <cstddef>

// Problem dims
#define BB    64
#define TT    512
#define IDIM  512
#define HH    512
#define RING  8

// Tiling
#define TM    16
#define TN    32
#define NBAND (BB/TM)       // 4
#define NQ    (HH/TN)       // 16 (CTA-level releases)
#define NCTA  128
#define NTHR  256

#define AS_STRIDE 1028
#define RMS 34              // Red m-stride (floats)
#define RWS 552             // Red slice stride (floats): 2208B = 32 mod 128B
#define NSLICE 16           // 8 warps x 2 k-halves

// SMEM layout (floats)
#define AS_OFF  0
#define WS_OFF  (TM*AS_STRIDE)                  // 16448
#define RED_OFF (WS_OFF + 512*64)               // + 32768
#define SMEM_FLOATS (RED_OFF + NSLICE*RWS)      // + 8832 = 58048 (~232.2 KB)

__device__ float g_h1[RING][BB][HH];
__device__ int   g_done1[TT*NBAND];
__device__ int   g_done2[TT*NBAND];

__global__ void rnn_init_counters() {
    int i = blockIdx.x * blockDim.x + threadIdx.x;
    if (i < TT*NBAND) { g_done1[i] = 0; g_done2[i] = 0; }
}

__device__ __forceinline__ int ld_acq(const int* p) {
    int v;
    asm volatile("ld.acquire.gpu.global.u32 %0, [%1];" : "=r"(v) : "l"(p));
    return v;
}
__device__ __forceinline__ void red_release(int* p) {
    asm volatile("red.release.gpu.global.add.u32 [%0], %1;" :: "l"(p), "r"(1) : "memory");
}
__device__ __forceinline__ void spin_ge(const int* p, int target) {
    while (ld_acq(p) < target) { }
}
__device__ __forceinline__ void fma2(unsigned long long& acc,
                                     unsigned long long a, unsigned long long b) {
    asm("fma.rn.f32x2 %0, %1, %2, %0;" : "+l"(acc) : "l"(a), "l"(b));
}
__device__ __forceinline__ float4 ldcg4(const float* p) {
    return __ldcg((const float4*)p);
}

// tanh(x) = 1 - 2/(exp(2x)+1); ex2.approx + rcp.approx + 1 Newton (abs err ~1e-7)
__device__ __forceinline__ float fast_tanh(float v) {
    float e;
    asm("ex2.approx.f32 %0, %1;" : "=f"(e) : "f"(v * 2.8853900817779268f));
    float d = e + 1.0f;
    float r;
    asm("rcp.approx.f32 %0, %1;" : "=f"(r) : "f"(d));
    r = r * (2.0f - d * r);
    return 1.0f - 2.0f * r;
}

// Store one float4 (k = 4*kk..4*kk+3 of row mm) into swizzled row-major As.
__device__ __forceinline__ void stage_f4(float* As, int mm, int kk, float4 v) {
    int idx = (kk*4) ^ ((mm >> 2) * 8);
    *(float4*)&As[mm*AS_STRIDE + idx] = v;
}

__global__ void __launch_bounds__(NTHR, 1) rnn_persistent(
    const float* __restrict__ x,    // [B,T,I]
    const float* __restrict__ h0,   // [L,B,H]
    const float* __restrict__ Wih,  // [L,H,I]
    const float* __restrict__ bih,  // [L,H]
    const float* __restrict__ Whh,  // [L,H,H]
    const float* __restrict__ bhh,  // [L,H]
    float* __restrict__ out)        // [B,T,H] then [L,B,H]
{
    extern __shared__ float smem[];
    float* As  = smem + AS_OFF;   // [16][1028] row-major, k-index XOR-swizzled
    float* Ws  = smem + WS_OFF;   // [512 kp][64]
    float* Red = smem + RED_OFF;  // [16 slice][16 m x RMS]

    const int bx    = blockIdx.x;
    const int layer = bx >> 6;
    const int j     = bx & 63;
    const int r     = j >> 4;
    const int q     = j & 15;
    const int tid   = threadIdx.x;
    const int w     = tid >> 5;          // warp id; warp kp slice [64w, 64w+64)
    const int lane  = tid & 31;
    const bool on_path = (w >= 4);       // warps 4-7 own the recurrent K-half

    // GEMM lane mapping: lane = kh*16 + rg*8 + cg
    const int kh   = lane >> 4;          // k-half of warp slice
    const int rg   = (lane >> 3) & 1;    // rows 8rg .. 8rg+7
    const int cg   = lane & 7;           // cols {2cg,2cg+1,16+2cg,17+2cg}
    const int kbase = 64*w + 32*kh;      // this lane's kp slice [kbase, kbase+32)
    const int xr1  = 16*rg;              // swizzle const, rows 8rg..8rg+3
    const int xr2  = 16*rg + 8;          // swizzle const, rows 8rg+4..8rg+7

    const float* Wi = Wih + (size_t)layer * HH * IDIM;
    const float* Wh = Whh + (size_t)layer * HH * HH;

    // one-time weight load: k-paired transposed; kp 0..255 = Wih, 256..511 = Whh
    for (int idx = tid; idx < TN*256; idx += NTHR) {
        int c   = idx >> 8;
        int kpl = idx & 255;
        float2 vi = __ldg((const float2*)(Wi + (size_t)(q*TN + c)*IDIM) + kpl);
        float2 vh = __ldg((const float2*)(Wh + (size_t)(q*TN + c)*HH)   + kpl);
        *(float2*)&Ws[(size_t)kpl*64 + c*2]       = vi;
        *(float2*)&Ws[(size_t)(256+kpl)*64 + c*2] = vh;
    }

    // per-warp staging constants: warp w owns As f4-columns [32w, 32w+32)
    const int c_st  = lane & 15;
    const int mr_st = lane >> 4;
    const int kk0   = 32*w + c_st;
    const int kk1   = kk0 + 16;
    const int s0    = on_path ? (kk0 - 128) : kk0;
    const int s1    = on_path ? (kk1 - 128) : kk1;

    // output mapping (reduce/store): 2 outputs per thread
    const int o0     = 2*tid;
    const int m_out  = o0 >> 5;
    const int c_out  = o0 & 31;
    const int brow_o = r*TM + m_out;
    const int hcol_o = q*TN + c_out;
    float2 bias;
    bias.x = bih[layer*HH + hcol_o]   + bhh[layer*HH + hcol_o];
    bias.y = bih[layer*HH + hcol_o+1] + bhh[layer*HH + hcol_o+1];

    __syncthreads();

    const float* Ab = As + (size_t)(8*rg)*AS_STRIDE;

    for (int t = 0; t < TT; ++t) {
        // ============ per-warp-group: wait + stage own columns ============
        if (!on_path) {
            if (layer == 0) {
                #pragma unroll
                for (int i = 0; i < 8; ++i) {
                    int mm = mr_st + 2*i;
                    const float4* xp = (const float4*)(x + ((size_t)(r*TM+mm)*TT + t)*IDIM);
                    stage_f4(As, mm, kk0, __ldg(xp + s0));
                    stage_f4(As, mm, kk1, __ldg(xp + s1));
                }
            } else {
                if (lane == 0) spin_ge(&g_done1[t*NBAND + r], NQ);
                __syncwarp();
                const float* hb = &g_h1[t&(RING-1)][r*TM][0];
                #pragma unroll
                for (int i = 0; i < 8; ++i) {
                    int mm = mr_st + 2*i;
                    const float* hp = hb + (size_t)mm*HH;
                    stage_f4(As, mm, kk0, ldcg4(hp + s0*4));
                    stage_f4(As, mm, kk1, ldcg4(hp + s1*4));
                }
            }
        } else {
            if (layer == 0) {
                if (lane == 0) {
                    if (t > 0)     spin_ge(&g_done1[(t-1)*NBAND + r], NQ);
                    if (t >= RING) spin_ge(&g_done2[(t-RING)*NBAND + r], NQ);
                }
                __syncwarp();
                #pragma unroll
                for (int i = 0; i < 8; ++i) {
                    int mm = mr_st + 2*i;
                    int b  = r*TM + mm;
                    const float* hp = (t == 0) ? (h0 + (size_t)b*HH)
                                               : &g_h1[(t-1)&(RING-1)][b][0];
                    stage_f4(As, mm, kk0, ldcg4(hp + s0*4));
                    stage_f4(As, mm, kk1, ldcg4(hp + s1*4));
                }
            } else {
                if (lane == 0 && t > 0) spin_ge(&g_done2[(t-1)*NBAND + r], NQ);
                __syncwarp();
                #pragma unroll
                for (int i = 0; i < 8; ++i) {
                    int mm = mr_st + 2*i;
                    int b  = r*TM + mm;
                    const float* hp = (t == 0) ? (h0 + (size_t)BB*HH + (size_t)b*HH)
                                               : (out + ((size_t)b*TT + (t-1))*HH);
                    stage_f4(As, mm, kk0, ldcg4(hp + s0*4));
                    stage_f4(As, mm, kk1, ldcg4(hp + s1*4));
                }
            }
        }
        __syncwarp();   // warp reads only its own staged columns

        // ---- GEMM: lane kp-slice [kbase,kbase+32), thread 8 rows x 4 cols, FMA2 ----
        unsigned long long acc[32];
        #pragma unroll
        for (int i = 0; i < 32; ++i) acc[i] = 0ull;

        const float* Wp = Ws + (size_t)kbase*64 + cg*4;
        #pragma unroll 4
        for (int i = 0; i < 32; ++i) {
            int k2  = 2*(kbase + i);
            int ka  = k2 ^ xr1;            // rows 8rg .. 8rg+3
            int kb  = k2 ^ xr2;            // rows 8rg+4 .. 8rg+7
            unsigned long long a0 = *(const unsigned long long*)(Ab + ka);
            unsigned long long a1 = *(const unsigned long long*)(Ab + AS_STRIDE   + ka);
            unsigned long long a2 = *(const unsigned long long*)(Ab + 2*AS_STRIDE + ka);
            unsigned long long a3 = *(const unsigned long long*)(Ab + 3*AS_STRIDE + ka);
            unsigned long long a4 = *(const unsigned long long*)(Ab + 4*AS_STRIDE + kb);
            unsigned long long a5 = *(const unsigned long long*)(Ab + 5*AS_STRIDE + kb);
            unsigned long long a6 = *(const unsigned long long*)(Ab + 6*AS_STRIDE + kb);
            unsigned long long a7 = *(const unsigned long long*)(Ab + 7*AS_STRIDE + kb);
            ulonglong2 W0 = *(const ulonglong2*)(Wp);        // cols 2cg, 2cg+1
            ulonglong2 W1 = *(const ulonglong2*)(Wp + 32);   // cols 16+2cg, 17+2cg
            fma2(acc[ 0], a0, W0.x); fma2(acc[ 1], a0, W0.y);
            fma2(acc[ 2], a0, W1.x); fma2(acc[ 3], a0, W1.y);
            fma2(acc[ 4], a1, W0.x); fma2(acc[ 5], a1, W0.y);
            fma2(acc[ 6], a1, W1.x); fma2(acc[ 7], a1, W1.y);
            fma2(acc[ 8], a2, W0.x); fma2(acc[ 9], a2, W0.y);
            fma2(acc[10], a2, W1.x); fma2(acc[11], a2, W1.y);
            fma2(acc[12], a3, W0.x); fma2(acc[13], a3, W0.y);
            fma2(acc[14], a3, W1.x); fma2(acc[15], a3, W1.y);
            fma2(acc[16], a4, W0.x); fma2(acc[17], a4, W0.y);
            fma2(acc[18], a4, W1.x); fma2(acc[19], a4, W1.y);
            fma2(acc[20], a5, W0.x); fma2(acc[21], a5, W0.y);
            fma2(acc[22], a5, W1.x); fma2(acc[23], a5, W1.y);
            fma2(acc[24], a6, W0.x); fma2(acc[25], a6, W0.y);
            fma2(acc[26], a6, W1.x); fma2(acc[27], a6, W1.y);
            fma2(acc[28], a7, W0.x); fma2(acc[29], a7, W0.y);
            fma2(acc[30], a7, W1.x); fma2(acc[31], a7, W1.y);
            Wp += 64;
        }

        // horizontal add (even-k + odd-k), partials to own slice (s = 2w + kh)
        {
            float* Rw = Red + (2*w + kh)*RWS + (8*rg)*RMS + cg*2;
            #pragma unroll
            for (int rr = 0; rr < 8; ++rr) {
                float lo0, hi0, lo1, hi1, lo2, hi2, lo3, hi3;
                asm("mov.b64 {%0, %1}, %2;" : "=f"(lo0), "=f"(hi0) : "l"(acc[rr*4+0]));
                asm("mov.b64 {%0, %1}, %2;" : "=f"(lo1), "=f"(hi1) : "l"(acc[rr*4+1]));
                asm("mov.b64 {%0, %1}, %2;" : "=f"(lo2), "=f"(hi2) : "l"(acc[rr*4+2]));
                asm("mov.b64 {%0, %1}, %2;" : "=f"(lo3), "=f"(hi3) : "l"(acc[rr*4+3]));
                *(float2*)(Rw + rr*RMS)      = make_float2(lo0+hi0, lo1+hi1);
                *(float2*)(Rw + rr*RMS + 16) = make_float2(lo2+hi2, lo3+hi3);
            }
        }
        __syncthreads();   // join warp groups: partials -> reduce

        // ---- cross-slice reduce (16 slices), bias, tanh, store ----
        float2 acc2 = make_float2(0.f, 0.f);
        const float* Rb = Red + m_out*RMS + c_out;
        #pragma unroll
        for (int ss = 0; ss < NSLICE; ++ss) {
            float2 v = *(const float2*)(Rb + ss*RWS);
            acc2.x += v.x; acc2.y += v.y;
        }
        float2 res;
        res.x = fast_tanh(acc2.x + bias.x);
        res.y = fast_tanh(acc2.y + bias.y);

        if (layer == 0) {
            *(float2*)&g_h1[t&(RING-1)][brow_o][hcol_o] = res;
            if (t == TT-1)
                *(float2*)(out + (size_t)BB*TT*HH + (size_t)brow_o*HH + hcol_o) = res;
        } else {
            *(float2*)(out + ((size_t)brow_o*TT + t)*HH + hcol_o) = res;
            if (t == TT-1)
                *(float2*)(out + (size_t)BB*TT*HH + (size_t)BB*HH
                               + (size_t)brow_o*HH + hcol_o) = res;
        }

        __syncthreads();   // all stores done before release
        if (tid == 0) {
            int* ctr = (layer == 0) ? &g_done1[t*NBAND + r] : &g_done2[t*NBAND + r];
            red_release(ctr);
        }
    }
}

extern "C" void kernel_launch(void* const* d_in, const int* in_sizes, int n_in,
                              void* d_out, int out_size)
{
    const float* x   = (const float*)d_in[0];
    const float* h0  = (const float*)d_in[1];
    const float* Wih = (const float*)d_in[2];
    const float* bih = (const float*)d_in[3];
    const float* Whh = (const float*)d_in[4];
    const float* bhh = (const float*)d_in[5];
    float* out = (float*)d_out;

    const size_t smem_bytes = (size_t)SMEM_FLOATS * sizeof(float); // ~232.2 KB
    cudaFuncSetAttribute(rnn_persistent,
                         cudaFuncAttributeMaxDynamicSharedMemorySize,
                         (int)smem_bytes);

    rnn_init_counters<<<(TT*NBAND + 255)/256, 256>>>();
    rnn_persistent<<<NCTA, NTHR, smem_bytes>>>(x, h0, Wih, bih, Whh, bhh, out);
}